// round 10
// baseline (speedup 1.0000x reference)
#include <cuda_runtime.h>
#include <cstdint>

#define T_SEQ 2048
#define NB    64
#define DIN   256
#define NH    256

#define NAN_PAT 0x7FC00000u

// scratch: precomputed input projection xw[t][b][h]  (128 MB, static — no allocs)
__device__ float g_xw[(size_t)T_SEQ * NB * NH];

// padded h index: +4 words per 32-float window (stride 36) -> conflict-free LDS.128
#define PHYS(k) ((k) + (((k) >> 5) << 2))
#define HPAD 288   // 256 + 8 windows * 4 pad

// xs row: +4 words per 64-float window -> the 4 k-group broadcast addresses
// land on distinct bank quads (words 0/4/8/12 mod 32) => conflict-free LDS.128
#define XPHYS(k) ((k) + (((k) >> 6) << 2))
#define XROW 272   // 256 + 4*4 pad

// ---------------- packed fp32x2 helpers (sm_100+) ----------------
__device__ __forceinline__ unsigned long long fma2(unsigned long long a,
                                                   unsigned long long b,
                                                   unsigned long long c) {
    unsigned long long d;
    asm("fma.rn.f32x2 %0, %1, %2, %3;" : "=l"(d) : "l"(a), "l"(b), "l"(c));
    return d;
}
__device__ __forceinline__ float f2sum(unsigned long long v) {
    float lo, hi;
    asm("mov.b64 {%0, %1}, %2;" : "=f"(lo), "=f"(hi) : "l"(v));
    return lo + hi;
}
__device__ __forceinline__ unsigned long long packf2(float lo, float hi) {
    unsigned long long r;
    asm("mov.b64 %0, {%1, %2};" : "=l"(r) : "f"(lo), "f"(hi));
    return r;
}
__device__ __forceinline__ uint32_t smem_u32(const void* p) {
    uint32_t a;
    asm("{ .reg .u64 t; cvta.to.shared.u64 t, %1; cvt.u32.u64 %0, t; }"
        : "=r"(a) : "l"(p));
    return a;
}
__device__ __forceinline__ uint32_t mapa_(uint32_t addr, int rank) {
    uint32_t r;
    asm("mapa.shared::cluster.u32 %0, %1, %2;" : "=r"(r) : "r"(addr), "r"(rank));
    return r;
}
__device__ __forceinline__ void cluster_sync_() {
    asm volatile("barrier.cluster.arrive.aligned;\n\t"
                 "barrier.cluster.wait.aligned;" ::: "memory");
}
__device__ __forceinline__ void st_cluster_b64(uint32_t addr, unsigned long long v) {
    asm volatile("st.shared::cluster.b64 [%0], %1;" :: "r"(addr), "l"(v) : "memory");
}
// volatile 16B smem load (poll + data in one)
__device__ __forceinline__ void ldv2(uint32_t a, unsigned long long& x,
                                     unsigned long long& y) {
    asm volatile("ld.volatile.shared.v2.u64 {%0, %1}, [%2];"
                 : "=l"(x), "=l"(y) : "r"(a) : "memory");
}
__device__ __forceinline__ void stv2(uint32_t a, unsigned long long x,
                                     unsigned long long y) {
    asm volatile("st.volatile.shared.v2.u64 [%0], {%1, %2};"
                 :: "r"(a), "l"(x), "l"(y) : "memory");
}
__device__ __forceinline__ void st32(uint32_t a, uint32_t v) {
    asm volatile("st.volatile.shared.u32 [%0], %1;" :: "r"(a), "r"(v) : "memory");
}
__device__ __forceinline__ float tanh_fast(float x) {
    float e = __expf(2.0f * x);
    return 1.0f - __fdividef(2.0f, e + 1.0f);
}

// =================================================================
// Kernel 1: input projection v2 — intra-warp reduce, no phase B.
//   grid (1024 row-chunks of 128, 2 col halves), 256 thr.
//   Warp w: 16 cols. Lane: cg=l&7 -> col pair (2cg, 2cg+1); kp=l>>3 ->
//   64-k quarter. Thread: 2 cols x 64 k weights in regs (64 u64).
//   Per row: 16 LDS.128 (broadcast, conflict-free) + 64 fma2 ->
//   2-level shfl.xor reduce -> writer lanes (kp==0) STG.64 coalesced.
//   One __syncthreads per 8-row block; next block LDG'd into regs first.
// =================================================================
__global__ void __launch_bounds__(256, 1)
xw_kernel(const float* __restrict__ x,
          const float* __restrict__ w_ih,
          const float* __restrict__ b_ih,
          const float* __restrict__ b_hh) {
    __shared__ __align__(16) float xs[2][8][XROW];

    const int tid  = threadIdx.x;
    const int w    = tid >> 5;
    const int l    = tid & 31;
    const int cg   = l & 7;                     // col pair within warp
    const int kp   = l >> 3;                    // k quarter 0..3
    const int half = blockIdx.y;
    const int rowbase0 = blockIdx.x * 128;
    const int j0   = half * 128 + w * 16 + 2 * cg;   // first of 2 cols
    const int k0   = kp * 64;
    const bool writer = (kp == 0);

    // register-resident weights: cols j0, j0+1, k in [k0, k0+64)
    unsigned long long wa[32], wb[32];
    {
        const unsigned long long* p0 =
            (const unsigned long long*)(w_ih + (size_t)j0 * DIN + k0);
        const unsigned long long* p1 =
            (const unsigned long long*)(w_ih + (size_t)(j0 + 1) * DIN + k0);
#pragma unroll
        for (int i = 0; i < 32; i++) { wa[i] = p0[i]; wb[i] = p1[i]; }
    }
    float bias0 = 0.f, bias1 = 0.f;
    if (writer) {
        bias0 = b_ih[j0] + b_hh[j0];
        bias1 = b_ih[j0 + 1] + b_hh[j0 + 1];
    }

    const float4* xg = (const float4*)x;
    // staging map: element q (0..511): row r=q>>6, chunk c4=q&63 ->
    // phys word 4*c4 + 4*(c4>>4)
    const int sr = tid >> 6, sc0 = tid & 63;
    const int sw0 = 4 * sc0 + 4 * (sc0 >> 4);

    {   // stage first 8 rows into buffer 0
        float4 a = xg[(size_t)(rowbase0 + sr) * 64 + sc0];
        float4 b = xg[(size_t)(rowbase0 + 4 + sr) * 64 + sc0];
        *(float4*)&xs[0][sr][sw0]     = a;
        *(float4*)&xs[0][sr + 4][sw0] = b;
    }
    __syncthreads();

    const int xbase = XPHYS(k0);     // word offset of my k-window in a row
    int p = 0;
    for (int it = 0; it < 16; it++) {
        const int rowbase = rowbase0 + it * 8;

        float4 n0, n1;
        if (it < 15) {               // prefetch next 8 rows into regs
            int nrb = rowbase + 8;
            n0 = xg[(size_t)(nrb + sr) * 64 + sc0];
            n1 = xg[(size_t)(nrb + 4 + sr) * 64 + sc0];
        }

#pragma unroll
        for (int r = 0; r < 8; r++) {
            const ulonglong2* xp = (const ulonglong2*)&xs[p][r][xbase];
            unsigned long long a0 = 0ull, a1 = 0ull;
#pragma unroll
            for (int i = 0; i < 16; i++) {
                ulonglong2 hv = xp[i];        // broadcast within kp-group
                a0 = fma2(wa[2 * i],     hv.x, a0);
                a0 = fma2(wa[2 * i + 1], hv.y, a0);
                a1 = fma2(wb[2 * i],     hv.x, a1);
                a1 = fma2(wb[2 * i + 1], hv.y, a1);
            }
            float v0 = f2sum(a0), v1 = f2sum(a1);
            v0 += __shfl_xor_sync(0xffffffffu, v0, 8);
            v1 += __shfl_xor_sync(0xffffffffu, v1, 8);
            v0 += __shfl_xor_sync(0xffffffffu, v0, 16);
            v1 += __shfl_xor_sync(0xffffffffu, v1, 16);
            if (writer) {
                float2 o = make_float2(v0 + bias0, v1 + bias1);
                *(float2*)&g_xw[(size_t)(rowbase + r) * NH + j0] = o;
            }
        }

        if (it < 15) {               // store prefetched rows to other buffer
            *(float4*)&xs[p ^ 1][sr][sw0]     = n0;
            *(float4*)&xs[p ^ 1][sr + 4][sw0] = n1;
            __syncthreads();         // buffer swap ready
            p ^= 1;
        }
    }
}

// =================================================================
// Kernel 2: recurrence v9 — barrier-free sentinel dataflow (UNCHANGED,
// proven best at 2198.6us). See R9 notes.
// =================================================================
__global__ void __launch_bounds__(256, 1) __cluster_dims__(2, 1, 1)
rnn_kernel(const float* __restrict__ w_hh, float* __restrict__ out) {
    __shared__ __align__(16) float hbuf[4][HPAD];   // 4 rotating slots

    const int tid  = threadIdx.x;
    const int w    = tid >> 5, l = tid & 31;
    const int cg   = l & 3,  kp = l >> 2;
    const int b    = blockIdx.x >> 1;
    const int c    = blockIdx.x & 1;
    const int peer = c ^ 1;
    const int j0   = c * 128 + w * 16 + cg * 4;    // 4 output cols (global)
    const int k0   = kp * 32;                      // contiguous 32-k window
    const bool writer = (kp == 0);

    // register-resident weights: rows j0..j0+3, k in [k0, k0+32)
    unsigned long long wv[4][16];
#pragma unroll
    for (int cc = 0; cc < 4; cc++) {
        const unsigned long long* row =
            (const unsigned long long*)(w_hh + (size_t)(j0 + cc) * NH + k0);
#pragma unroll
        for (int i = 0; i < 16; i++) wv[cc][i] = row[i];
    }

    // slot 0 = h0 = 0 (valid); slots 1..3 = sentinel
    for (int i = tid; i < HPAD; i += 256) hbuf[0][i] = 0.f;
    for (int i = HPAD + tid; i < 4 * HPAD; i += 256)
        ((uint32_t*)hbuf)[i] = NAN_PAT;

    // per-lane addresses
    uint32_t wbase[4];                             // my k-window, per slot
#pragma unroll
    for (int s4 = 0; s4 < 4; s4++) wbase[s4] = smem_u32(&hbuf[s4][PHYS(k0)]);

    const int pj = PHYS(j0);
    uint32_t lcw[4], rcw[4];                       // writer chunk, local/remote
#pragma unroll
    for (int s4 = 0; s4 < 4; s4++) {
        lcw[s4] = smem_u32(&hbuf[s4][pj]);
        rcw[s4] = mapa_(lcw[s4], peer);
    }
    // reset duty: tid<128 resets head word tid of each slot
    uint32_t rst[4];
    {
        int chunk = tid >> 1, half = tid & 1;
        int off = 36 * (chunk >> 3) + 4 * (chunk & 7) + half * 2;
#pragma unroll
        for (int s4 = 0; s4 < 4; s4++) rst[s4] = smem_u32(&hbuf[s4][off]);
    }

    cluster_sync_();   // init visible cluster-wide before any remote push

    float4 xc, x1;
    if (writer) {
        xc = *(const float4*)&g_xw[(size_t)b * NH + j0];
        x1 = *(const float4*)&g_xw[((size_t)NB + b) * NH + j0];
    }

    for (int s = 0; s < T_SEQ; s++) {
        const int sp = s & 3, sq = (s + 1) & 3, sr = (s + 2) & 3;

        // ---- poll h(s): loads are the data; chunk present iff heads!=NaN --
        unsigned long long hx[8], hy[8];
        const uint32_t wb = wbase[sp];
        bool ok;
        do {
            ok = true;
#pragma unroll
            for (int i = 0; i < 8; i++) {
                ldv2(wb + 16u * i, hx[i], hy[i]);
                ok &= ((uint32_t)hx[i] != NAN_PAT) & ((uint32_t)hy[i] != NAN_PAT);
            }
        } while (!__all_sync(0xffffffffu, ok));

        // ---- reset heads of slot sr (h(s-2) slot -> future h(s+2)).
        //      Emitted BEFORE this warp's pushes (program order gates peer).
        if (tid < 128) st32(rst[sr], NAN_PAT);

        // ---- GEMV slice: 4 cols x 32 k (64 fma2) ----
        unsigned long long a0 = 0ull, a1 = 0ull, a2 = 0ull, a3 = 0ull;
#pragma unroll
        for (int i = 0; i < 8; i++) {
            a0 = fma2(wv[0][2 * i], hx[i], a0);
            a0 = fma2(wv[0][2 * i + 1], hy[i], a0);
            a1 = fma2(wv[1][2 * i], hx[i], a1);
            a1 = fma2(wv[1][2 * i + 1], hy[i], a1);
            a2 = fma2(wv[2][2 * i], hx[i], a2);
            a2 = fma2(wv[2][2 * i + 1], hy[i], a2);
            a3 = fma2(wv[3][2 * i], hx[i], a3);
            a3 = fma2(wv[3][2 * i + 1], hy[i], a3);
        }
        float v0 = f2sum(a0), v1 = f2sum(a1), v2 = f2sum(a2), v3 = f2sum(a3);
#pragma unroll
        for (int d = 4; d <= 16; d <<= 1) {        // butterfly over 8 k-parts
            v0 += __shfl_xor_sync(0xffffffffu, v0, d);
            v1 += __shfl_xor_sync(0xffffffffu, v1, d);
            v2 += __shfl_xor_sync(0xffffffffu, v2, d);
            v3 += __shfl_xor_sync(0xffffffffu, v3, d);
        }

        if (writer) {
            v0 = tanh_fast(v0 + xc.x);
            v1 = tanh_fast(v1 + xc.y);
            v2 = tanh_fast(v2 + xc.z);
            v3 = tanh_fast(v3 + xc.w);
            if (s + 1 < T_SEQ) {
                unsigned long long p01 = packf2(v0, v1), p23 = packf2(v2, v3);
                stv2(lcw[sq], p01, p23);           // local chunk
                st_cluster_b64(rcw[sq],     p01);  // remote copy
                st_cluster_b64(rcw[sq] + 8, p23);
            }
            // off-critical-path tail
            *(float4*)(out + ((size_t)s * NB + b) * NH + j0) =
                make_float4(v0, v1, v2, v3);
            xc = x1;
            if (s + 2 < T_SEQ)
                x1 = *(const float4*)&g_xw[((size_t)(s + 2) * NB + b) * NH + j0];
        }
    }
    cluster_sync_();   // keep smem alive for in-flight peer stores
}

// =================================================================
extern "C" void kernel_launch(void* const* d_in, const int* in_sizes, int n_in,
                              void* d_out, int out_size) {
    const float* x    = (const float*)d_in[0];
    const float* w_ih = (const float*)d_in[1];
    const float* w_hh = (const float*)d_in[2];
    const float* b_ih = (const float*)d_in[3];
    const float* b_hh = (const float*)d_in[4];
    float* out = (float*)d_out;

    dim3 g1(1024, 2);
    xw_kernel<<<g1, 256>>>(x, w_ih, b_ih, b_hh);
    rnn_kernel<<<128, 256>>>(w_hh, out);
}

// round 11
// speedup vs baseline: 1.0456x; 1.0456x over previous
#include <cuda_runtime.h>
#include <cstdint>

#define T_SEQ 2048
#define NB    64
#define DIN   256
#define NH    256

#define NAN_PAT 0x7FC00000u

// scratch: precomputed input projection xw[t][b][h]  (128 MB, static — no allocs)
__device__ float g_xw[(size_t)T_SEQ * NB * NH];

// padded h index: +4 words per 32-float window (stride 36) -> conflict-free LDS.128
#define PHYS(k) ((k) + (((k) >> 5) << 2))
#define HPAD 288   // 256 + 8 windows * 4 pad

// xs row: +4 words per 64-float window -> the 4 k-group broadcast addresses
// land on distinct bank quads (words 0/4/8/12 mod 32) => conflict-free LDS.128
#define XPHYS(k) ((k) + (((k) >> 6) << 2))
#define XROW 272   // 256 + 4*4 pad

// ---------------- packed fp32x2 helpers (sm_100+) ----------------
__device__ __forceinline__ unsigned long long fma2(unsigned long long a,
                                                   unsigned long long b,
                                                   unsigned long long c) {
    unsigned long long d;
    asm("fma.rn.f32x2 %0, %1, %2, %3;" : "=l"(d) : "l"(a), "l"(b), "l"(c));
    return d;
}
__device__ __forceinline__ float f2sum(unsigned long long v) {
    float lo, hi;
    asm("mov.b64 {%0, %1}, %2;" : "=f"(lo), "=f"(hi) : "l"(v));
    return lo + hi;
}
__device__ __forceinline__ unsigned long long packf2(float lo, float hi) {
    unsigned long long r;
    asm("mov.b64 %0, {%1, %2};" : "=l"(r) : "f"(lo), "f"(hi));
    return r;
}
__device__ __forceinline__ uint32_t smem_u32(const void* p) {
    uint32_t a;
    asm("{ .reg .u64 t; cvta.to.shared.u64 t, %1; cvt.u32.u64 %0, t; }"
        : "=r"(a) : "l"(p));
    return a;
}
__device__ __forceinline__ uint32_t mapa_(uint32_t addr, int rank) {
    uint32_t r;
    asm("mapa.shared::cluster.u32 %0, %1, %2;" : "=r"(r) : "r"(addr), "r"(rank));
    return r;
}
__device__ __forceinline__ void cluster_sync_() {
    asm volatile("barrier.cluster.arrive.aligned;\n\t"
                 "barrier.cluster.wait.aligned;" ::: "memory");
}
__device__ __forceinline__ void st_cluster_b64(uint32_t addr, unsigned long long v) {
    asm volatile("st.shared::cluster.b64 [%0], %1;" :: "r"(addr), "l"(v) : "memory");
}
// volatile 16B smem load (poll + data in one)
__device__ __forceinline__ void ldv2(uint32_t a, unsigned long long& x,
                                     unsigned long long& y) {
    asm volatile("ld.volatile.shared.v2.u64 {%0, %1}, [%2];"
                 : "=l"(x), "=l"(y) : "r"(a) : "memory");
}
__device__ __forceinline__ void stv2(uint32_t a, unsigned long long x,
                                     unsigned long long y) {
    asm volatile("st.volatile.shared.v2.u64 [%0], {%1, %2};"
                 :: "r"(a), "l"(x), "l"(y) : "memory");
}
__device__ __forceinline__ void st32(uint32_t a, uint32_t v) {
    asm volatile("st.volatile.shared.u32 [%0], %1;" :: "r"(a), "r"(v) : "memory");
}
__device__ __forceinline__ float tanh_fast(float x) {
    float e = __expf(2.0f * x);
    return 1.0f - __fdividef(2.0f, e + 1.0f);
}

// =================================================================
// Kernel 1: input projection v2 — intra-warp reduce, no phase B.
//   grid (1024 row-chunks of 128, 2 col halves), 256 thr.
//   Warp w: 16 cols. Lane: cg=l&7 -> col pair (2cg, 2cg+1); kp=l>>3 ->
//   64-k quarter. Thread: 2 cols x 64 k weights in regs (64 u64).
//   Per row: 16 LDS.128 (broadcast, conflict-free) + 64 fma2 ->
//   2-level shfl.xor reduce -> writer lanes (kp==0) STG.64 coalesced.
//   One __syncthreads per 8-row block; next block LDG'd into regs first.
// =================================================================
__global__ void __launch_bounds__(256, 1)
xw_kernel(const float* __restrict__ x,
          const float* __restrict__ w_ih,
          const float* __restrict__ b_ih,
          const float* __restrict__ b_hh) {
    __shared__ __align__(16) float xs[2][8][XROW];

    const int tid  = threadIdx.x;
    const int w    = tid >> 5;
    const int l    = tid & 31;
    const int cg   = l & 7;                     // col pair within warp
    const int kp   = l >> 3;                    // k quarter 0..3
    const int half = blockIdx.y;
    const int rowbase0 = blockIdx.x * 128;
    const int j0   = half * 128 + w * 16 + 2 * cg;   // first of 2 cols
    const int k0   = kp * 64;
    const bool writer = (kp == 0);

    // register-resident weights: cols j0, j0+1, k in [k0, k0+64)
    unsigned long long wa[32], wb[32];
    {
        const unsigned long long* p0 =
            (const unsigned long long*)(w_ih + (size_t)j0 * DIN + k0);
        const unsigned long long* p1 =
            (const unsigned long long*)(w_ih + (size_t)(j0 + 1) * DIN + k0);
#pragma unroll
        for (int i = 0; i < 32; i++) { wa[i] = p0[i]; wb[i] = p1[i]; }
    }
    float bias0 = 0.f, bias1 = 0.f;
    if (writer) {
        bias0 = b_ih[j0] + b_hh[j0];
        bias1 = b_ih[j0 + 1] + b_hh[j0 + 1];
    }

    const float4* xg = (const float4*)x;
    // staging map: element q (0..511): row r=q>>6, chunk c4=q&63 ->
    // phys word 4*c4 + 4*(c4>>4)
    const int sr = tid >> 6, sc0 = tid & 63;
    const int sw0 = 4 * sc0 + 4 * (sc0 >> 4);

    {   // stage first 8 rows into buffer 0
        float4 a = xg[(size_t)(rowbase0 + sr) * 64 + sc0];
        float4 b = xg[(size_t)(rowbase0 + 4 + sr) * 64 + sc0];
        *(float4*)&xs[0][sr][sw0]     = a;
        *(float4*)&xs[0][sr + 4][sw0] = b;
    }
    __syncthreads();

    const int xbase = XPHYS(k0);     // word offset of my k-window in a row
    int p = 0;
    for (int it = 0; it < 16; it++) {
        const int rowbase = rowbase0 + it * 8;

        float4 n0, n1;
        if (it < 15) {               // prefetch next 8 rows into regs
            int nrb = rowbase + 8;
            n0 = xg[(size_t)(nrb + sr) * 64 + sc0];
            n1 = xg[(size_t)(nrb + 4 + sr) * 64 + sc0];
        }

#pragma unroll
        for (int r = 0; r < 8; r++) {
            const ulonglong2* xp = (const ulonglong2*)&xs[p][r][xbase];
            unsigned long long a0 = 0ull, a1 = 0ull;
#pragma unroll
            for (int i = 0; i < 16; i++) {
                ulonglong2 hv = xp[i];        // broadcast within kp-group
                a0 = fma2(wa[2 * i],     hv.x, a0);
                a0 = fma2(wa[2 * i + 1], hv.y, a0);
                a1 = fma2(wb[2 * i],     hv.x, a1);
                a1 = fma2(wb[2 * i + 1], hv.y, a1);
            }
            float v0 = f2sum(a0), v1 = f2sum(a1);
            v0 += __shfl_xor_sync(0xffffffffu, v0, 8);
            v1 += __shfl_xor_sync(0xffffffffu, v1, 8);
            v0 += __shfl_xor_sync(0xffffffffu, v0, 16);
            v1 += __shfl_xor_sync(0xffffffffu, v1, 16);
            if (writer) {
                float2 o = make_float2(v0 + bias0, v1 + bias1);
                *(float2*)&g_xw[(size_t)(rowbase + r) * NH + j0] = o;
            }
        }

        if (it < 15) {               // store prefetched rows to other buffer
            *(float4*)&xs[p ^ 1][sr][sw0]     = n0;
            *(float4*)&xs[p ^ 1][sr + 4][sw0] = n1;
            __syncthreads();         // buffer swap ready
            p ^= 1;
        }
    }
}

// =================================================================
// Kernel 2: recurrence v9 — barrier-free sentinel dataflow (UNCHANGED,
// proven best at 2198.6us). See R9 notes.
// =================================================================
__global__ void __launch_bounds__(256, 1) __cluster_dims__(2, 1, 1)
rnn_kernel(const float* __restrict__ w_hh, float* __restrict__ out) {
    __shared__ __align__(16) float hbuf[4][HPAD];   // 4 rotating slots

    const int tid  = threadIdx.x;
    const int w    = tid >> 5, l = tid & 31;
    const int cg   = l & 3,  kp = l >> 2;
    const int b    = blockIdx.x >> 1;
    const int c    = blockIdx.x & 1;
    const int peer = c ^ 1;
    const int j0   = c * 128 + w * 16 + cg * 4;    // 4 output cols (global)
    const int k0   = kp * 32;                      // contiguous 32-k window
    const bool writer = (kp == 0);

    // register-resident weights: rows j0..j0+3, k in [k0, k0+32)
    unsigned long long wv[4][16];
#pragma unroll
    for (int cc = 0; cc < 4; cc++) {
        const unsigned long long* row =
            (const unsigned long long*)(w_hh + (size_t)(j0 + cc) * NH + k0);
#pragma unroll
        for (int i = 0; i < 16; i++) wv[cc][i] = row[i];
    }

    // slot 0 = h0 = 0 (valid); slots 1..3 = sentinel
    for (int i = tid; i < HPAD; i += 256) hbuf[0][i] = 0.f;
    for (int i = HPAD + tid; i < 4 * HPAD; i += 256)
        ((uint32_t*)hbuf)[i] = NAN_PAT;

    // per-lane addresses
    uint32_t wbase[4];                             // my k-window, per slot
#pragma unroll
    for (int s4 = 0; s4 < 4; s4++) wbase[s4] = smem_u32(&hbuf[s4][PHYS(k0)]);

    const int pj = PHYS(j0);
    uint32_t lcw[4], rcw[4];                       // writer chunk, local/remote
#pragma unroll
    for (int s4 = 0; s4 < 4; s4++) {
        lcw[s4] = smem_u32(&hbuf[s4][pj]);
        rcw[s4] = mapa_(lcw[s4], peer);
    }
    // reset duty: tid<128 resets head word tid of each slot
    uint32_t rst[4];
    {
        int chunk = tid >> 1, half = tid & 1;
        int off = 36 * (chunk >> 3) + 4 * (chunk & 7) + half * 2;
#pragma unroll
        for (int s4 = 0; s4 < 4; s4++) rst[s4] = smem_u32(&hbuf[s4][off]);
    }

    cluster_sync_();   // init visible cluster-wide before any remote push

    float4 xc, x1;
    if (writer) {
        xc = *(const float4*)&g_xw[(size_t)b * NH + j0];
        x1 = *(const float4*)&g_xw[((size_t)NB + b) * NH + j0];
    }

    for (int s = 0; s < T_SEQ; s++) {
        const int sp = s & 3, sq = (s + 1) & 3, sr = (s + 2) & 3;

        // ---- poll h(s): loads are the data; chunk present iff heads!=NaN --
        unsigned long long hx[8], hy[8];
        const uint32_t wb = wbase[sp];
        bool ok;
        do {
            ok = true;
#pragma unroll
            for (int i = 0; i < 8; i++) {
                ldv2(wb + 16u * i, hx[i], hy[i]);
                ok &= ((uint32_t)hx[i] != NAN_PAT) & ((uint32_t)hy[i] != NAN_PAT);
            }
        } while (!__all_sync(0xffffffffu, ok));

        // ---- reset heads of slot sr (h(s-2) slot -> future h(s+2)).
        //      Emitted BEFORE this warp's pushes (program order gates peer).
        if (tid < 128) st32(rst[sr], NAN_PAT);

        // ---- GEMV slice: 4 cols x 32 k (64 fma2) ----
        unsigned long long a0 = 0ull, a1 = 0ull, a2 = 0ull, a3 = 0ull;
#pragma unroll
        for (int i = 0; i < 8; i++) {
            a0 = fma2(wv[0][2 * i], hx[i], a0);
            a0 = fma2(wv[0][2 * i + 1], hy[i], a0);
            a1 = fma2(wv[1][2 * i], hx[i], a1);
            a1 = fma2(wv[1][2 * i + 1], hy[i], a1);
            a2 = fma2(wv[2][2 * i], hx[i], a2);
            a2 = fma2(wv[2][2 * i + 1], hy[i], a2);
            a3 = fma2(wv[3][2 * i], hx[i], a3);
            a3 = fma2(wv[3][2 * i + 1], hy[i], a3);
        }
        float v0 = f2sum(a0), v1 = f2sum(a1), v2 = f2sum(a2), v3 = f2sum(a3);
#pragma unroll
        for (int d = 4; d <= 16; d <<= 1) {        // butterfly over 8 k-parts
            v0 += __shfl_xor_sync(0xffffffffu, v0, d);
            v1 += __shfl_xor_sync(0xffffffffu, v1, d);
            v2 += __shfl_xor_sync(0xffffffffu, v2, d);
            v3 += __shfl_xor_sync(0xffffffffu, v3, d);
        }

        if (writer) {
            v0 = tanh_fast(v0 + xc.x);
            v1 = tanh_fast(v1 + xc.y);
            v2 = tanh_fast(v2 + xc.z);
            v3 = tanh_fast(v3 + xc.w);
            if (s + 1 < T_SEQ) {
                unsigned long long p01 = packf2(v0, v1), p23 = packf2(v2, v3);
                stv2(lcw[sq], p01, p23);           // local chunk
                st_cluster_b64(rcw[sq],     p01);  // remote copy
                st_cluster_b64(rcw[sq] + 8, p23);
            }
            // off-critical-path tail
            *(float4*)(out + ((size_t)s * NB + b) * NH + j0) =
                make_float4(v0, v1, v2, v3);
            xc = x1;
            if (s + 2 < T_SEQ)
                x1 = *(const float4*)&g_xw[((size_t)(s + 2) * NB + b) * NH + j0];
        }
    }
    cluster_sync_();   // keep smem alive for in-flight peer stores
}

// =================================================================
extern "C" void kernel_launch(void* const* d_in, const int* in_sizes, int n_in,
                              void* d_out, int out_size) {
    const float* x    = (const float*)d_in[0];
    const float* w_ih = (const float*)d_in[1];
    const float* w_hh = (const float*)d_in[2];
    const float* b_ih = (const float*)d_in[3];
    const float* b_hh = (const float*)d_in[4];
    float* out = (float*)d_out;

    dim3 g1(1024, 2);
    xw_kernel<<<g1, 256>>>(x, w_ih, b_ih, b_hh);
    rnn_kernel<<<128, 256>>>(w_hh, out);
}

// round 12
// speedup vs baseline: 1.0480x; 1.0023x over previous
#include <cuda_runtime.h>
#include <cstdint>

#define T_SEQ 2048
#define NB    64
#define DIN   256
#define NH    256

#define NAN_PAT 0x7FC00000u

// scratch: precomputed input projection xw[t][b][h]  (128 MB, static — no allocs)
__device__ float g_xw[(size_t)T_SEQ * NB * NH];

// padded h index: +4 words per 32-float window (stride 36) -> conflict-free LDS.128
#define PHYS(k) ((k) + (((k) >> 5) << 2))
#define HPAD 288   // 256 + 8 windows * 4 pad

// xs row: +4 words per 64-float window -> the 4 k-group broadcast addresses
// land on distinct bank quads (words 0/4/8/12 mod 32) => conflict-free LDS.128
#define XPHYS(k) ((k) + (((k) >> 6) << 2))
#define XROW 272   // 256 + 4*4 pad

// ---------------- packed fp32x2 helpers (sm_100+) ----------------
__device__ __forceinline__ unsigned long long fma2(unsigned long long a,
                                                   unsigned long long b,
                                                   unsigned long long c) {
    unsigned long long d;
    asm("fma.rn.f32x2 %0, %1, %2, %3;" : "=l"(d) : "l"(a), "l"(b), "l"(c));
    return d;
}
__device__ __forceinline__ float f2sum(unsigned long long v) {
    float lo, hi;
    asm("mov.b64 {%0, %1}, %2;" : "=f"(lo), "=f"(hi) : "l"(v));
    return lo + hi;
}
__device__ __forceinline__ unsigned long long packf2(float lo, float hi) {
    unsigned long long r;
    asm("mov.b64 %0, {%1, %2};" : "=l"(r) : "f"(lo), "f"(hi));
    return r;
}
__device__ __forceinline__ uint32_t smem_u32(const void* p) {
    uint32_t a;
    asm("{ .reg .u64 t; cvta.to.shared.u64 t, %1; cvt.u32.u64 %0, t; }"
        : "=r"(a) : "l"(p));
    return a;
}
__device__ __forceinline__ uint32_t mapa_(uint32_t addr, int rank) {
    uint32_t r;
    asm("mapa.shared::cluster.u32 %0, %1, %2;" : "=r"(r) : "r"(addr), "r"(rank));
    return r;
}
__device__ __forceinline__ void cluster_sync_() {
    asm volatile("barrier.cluster.arrive.aligned;\n\t"
                 "barrier.cluster.wait.aligned;" ::: "memory");
}
__device__ __forceinline__ void st_cluster_b64(uint32_t addr, unsigned long long v) {
    asm volatile("st.shared::cluster.b64 [%0], %1;" :: "r"(addr), "l"(v) : "memory");
}
// volatile 16B smem load (poll + data in one)
__device__ __forceinline__ void ldv2(uint32_t a, unsigned long long& x,
                                     unsigned long long& y) {
    asm volatile("ld.volatile.shared.v2.u64 {%0, %1}, [%2];"
                 : "=l"(x), "=l"(y) : "r"(a) : "memory");
}
__device__ __forceinline__ void stv2(uint32_t a, unsigned long long x,
                                     unsigned long long y) {
    asm volatile("st.volatile.shared.v2.u64 [%0], {%1, %2};"
                 :: "r"(a), "l"(x), "l"(y) : "memory");
}
__device__ __forceinline__ void st32(uint32_t a, uint32_t v) {
    asm volatile("st.volatile.shared.u32 [%0], %1;" :: "r"(a), "r"(v) : "memory");
}
__device__ __forceinline__ float tanh_fast(float x) {
    float e = __expf(2.0f * x);
    return 1.0f - __fdividef(2.0f, e + 1.0f);
}

// =================================================================
// Kernel 1: input projection v2 — intra-warp reduce, no phase B.
//   grid (1024 row-chunks of 128, 2 col halves), 256 thr.
//   Warp w: 16 cols. Lane: cg=l&7 -> col pair (2cg, 2cg+1); kp=l>>3 ->
//   64-k quarter. Thread: 2 cols x 64 k weights in regs (64 u64).
//   Per row: 16 LDS.128 (broadcast, conflict-free) + 64 fma2 ->
//   2-level shfl.xor reduce -> writer lanes (kp==0) STG.64 coalesced.
//   One __syncthreads per 8-row block; next block LDG'd into regs first.
// =================================================================
__global__ void __launch_bounds__(256, 1)
xw_kernel(const float* __restrict__ x,
          const float* __restrict__ w_ih,
          const float* __restrict__ b_ih,
          const float* __restrict__ b_hh) {
    __shared__ __align__(16) float xs[2][8][XROW];

    const int tid  = threadIdx.x;
    const int w    = tid >> 5;
    const int l    = tid & 31;
    const int cg   = l & 7;                     // col pair within warp
    const int kp   = l >> 3;                    // k quarter 0..3
    const int half = blockIdx.y;
    const int rowbase0 = blockIdx.x * 128;
    const int j0   = half * 128 + w * 16 + 2 * cg;   // first of 2 cols
    const int k0   = kp * 64;
    const bool writer = (kp == 0);

    // register-resident weights: cols j0, j0+1, k in [k0, k0+64)
    unsigned long long wa[32], wb[32];
    {
        const unsigned long long* p0 =
            (const unsigned long long*)(w_ih + (size_t)j0 * DIN + k0);
        const unsigned long long* p1 =
            (const unsigned long long*)(w_ih + (size_t)(j0 + 1) * DIN + k0);
#pragma unroll
        for (int i = 0; i < 32; i++) { wa[i] = p0[i]; wb[i] = p1[i]; }
    }
    float bias0 = 0.f, bias1 = 0.f;
    if (writer) {
        bias0 = b_ih[j0] + b_hh[j0];
        bias1 = b_ih[j0 + 1] + b_hh[j0 + 1];
    }

    const float4* xg = (const float4*)x;
    // staging map: element q (0..511): row r=q>>6, chunk c4=q&63 ->
    // phys word 4*c4 + 4*(c4>>4)
    const int sr = tid >> 6, sc0 = tid & 63;
    const int sw0 = 4 * sc0 + 4 * (sc0 >> 4);

    {   // stage first 8 rows into buffer 0
        float4 a = xg[(size_t)(rowbase0 + sr) * 64 + sc0];
        float4 b = xg[(size_t)(rowbase0 + 4 + sr) * 64 + sc0];
        *(float4*)&xs[0][sr][sw0]     = a;
        *(float4*)&xs[0][sr + 4][sw0] = b;
    }
    __syncthreads();

    const int xbase = XPHYS(k0);     // word offset of my k-window in a row
    int p = 0;
    for (int it = 0; it < 16; it++) {
        const int rowbase = rowbase0 + it * 8;

        float4 n0, n1;
        if (it < 15) {               // prefetch next 8 rows into regs
            int nrb = rowbase + 8;
            n0 = xg[(size_t)(nrb + sr) * 64 + sc0];
            n1 = xg[(size_t)(nrb + 4 + sr) * 64 + sc0];
        }

#pragma unroll
        for (int r = 0; r < 8; r++) {
            const ulonglong2* xp = (const ulonglong2*)&xs[p][r][xbase];
            unsigned long long a0 = 0ull, a1 = 0ull;
#pragma unroll
            for (int i = 0; i < 16; i++) {
                ulonglong2 hv = xp[i];        // broadcast within kp-group
                a0 = fma2(wa[2 * i],     hv.x, a0);
                a0 = fma2(wa[2 * i + 1], hv.y, a0);
                a1 = fma2(wb[2 * i],     hv.x, a1);
                a1 = fma2(wb[2 * i + 1], hv.y, a1);
            }
            float v0 = f2sum(a0), v1 = f2sum(a1);
            v0 += __shfl_xor_sync(0xffffffffu, v0, 8);
            v1 += __shfl_xor_sync(0xffffffffu, v1, 8);
            v0 += __shfl_xor_sync(0xffffffffu, v0, 16);
            v1 += __shfl_xor_sync(0xffffffffu, v1, 16);
            if (writer) {
                float2 o = make_float2(v0 + bias0, v1 + bias1);
                *(float2*)&g_xw[(size_t)(rowbase + r) * NH + j0] = o;
            }
        }

        if (it < 15) {               // store prefetched rows to other buffer
            *(float4*)&xs[p ^ 1][sr][sw0]     = n0;
            *(float4*)&xs[p ^ 1][sr + 4][sw0] = n1;
            __syncthreads();         // buffer swap ready
            p ^= 1;
        }
    }
}

// =================================================================
// Kernel 2: recurrence v9 — barrier-free sentinel dataflow (UNCHANGED,
// proven best at 2198.6us). See R9 notes.
// =================================================================
__global__ void __launch_bounds__(256, 1) __cluster_dims__(2, 1, 1)
rnn_kernel(const float* __restrict__ w_hh, float* __restrict__ out) {
    __shared__ __align__(16) float hbuf[4][HPAD];   // 4 rotating slots

    const int tid  = threadIdx.x;
    const int w    = tid >> 5, l = tid & 31;
    const int cg   = l & 3,  kp = l >> 2;
    const int b    = blockIdx.x >> 1;
    const int c    = blockIdx.x & 1;
    const int peer = c ^ 1;
    const int j0   = c * 128 + w * 16 + cg * 4;    // 4 output cols (global)
    const int k0   = kp * 32;                      // contiguous 32-k window
    const bool writer = (kp == 0);

    // register-resident weights: rows j0..j0+3, k in [k0, k0+32)
    unsigned long long wv[4][16];
#pragma unroll
    for (int cc = 0; cc < 4; cc++) {
        const unsigned long long* row =
            (const unsigned long long*)(w_hh + (size_t)(j0 + cc) * NH + k0);
#pragma unroll
        for (int i = 0; i < 16; i++) wv[cc][i] = row[i];
    }

    // slot 0 = h0 = 0 (valid); slots 1..3 = sentinel
    for (int i = tid; i < HPAD; i += 256) hbuf[0][i] = 0.f;
    for (int i = HPAD + tid; i < 4 * HPAD; i += 256)
        ((uint32_t*)hbuf)[i] = NAN_PAT;

    // per-lane addresses
    uint32_t wbase[4];                             // my k-window, per slot
#pragma unroll
    for (int s4 = 0; s4 < 4; s4++) wbase[s4] = smem_u32(&hbuf[s4][PHYS(k0)]);

    const int pj = PHYS(j0);
    uint32_t lcw[4], rcw[4];                       // writer chunk, local/remote
#pragma unroll
    for (int s4 = 0; s4 < 4; s4++) {
        lcw[s4] = smem_u32(&hbuf[s4][pj]);
        rcw[s4] = mapa_(lcw[s4], peer);
    }
    // reset duty: tid<128 resets head word tid of each slot
    uint32_t rst[4];
    {
        int chunk = tid >> 1, half = tid & 1;
        int off = 36 * (chunk >> 3) + 4 * (chunk & 7) + half * 2;
#pragma unroll
        for (int s4 = 0; s4 < 4; s4++) rst[s4] = smem_u32(&hbuf[s4][off]);
    }

    cluster_sync_();   // init visible cluster-wide before any remote push

    float4 xc, x1;
    if (writer) {
        xc = *(const float4*)&g_xw[(size_t)b * NH + j0];
        x1 = *(const float4*)&g_xw[((size_t)NB + b) * NH + j0];
    }

    for (int s = 0; s < T_SEQ; s++) {
        const int sp = s & 3, sq = (s + 1) & 3, sr = (s + 2) & 3;

        // ---- poll h(s): loads are the data; chunk present iff heads!=NaN --
        unsigned long long hx[8], hy[8];
        const uint32_t wb = wbase[sp];
        bool ok;
        do {
            ok = true;
#pragma unroll
            for (int i = 0; i < 8; i++) {
                ldv2(wb + 16u * i, hx[i], hy[i]);
                ok &= ((uint32_t)hx[i] != NAN_PAT) & ((uint32_t)hy[i] != NAN_PAT);
            }
        } while (!__all_sync(0xffffffffu, ok));

        // ---- reset heads of slot sr (h(s-2) slot -> future h(s+2)).
        //      Emitted BEFORE this warp's pushes (program order gates peer).
        if (tid < 128) st32(rst[sr], NAN_PAT);

        // ---- GEMV slice: 4 cols x 32 k (64 fma2) ----
        unsigned long long a0 = 0ull, a1 = 0ull, a2 = 0ull, a3 = 0ull;
#pragma unroll
        for (int i = 0; i < 8; i++) {
            a0 = fma2(wv[0][2 * i], hx[i], a0);
            a0 = fma2(wv[0][2 * i + 1], hy[i], a0);
            a1 = fma2(wv[1][2 * i], hx[i], a1);
            a1 = fma2(wv[1][2 * i + 1], hy[i], a1);
            a2 = fma2(wv[2][2 * i], hx[i], a2);
            a2 = fma2(wv[2][2 * i + 1], hy[i], a2);
            a3 = fma2(wv[3][2 * i], hx[i], a3);
            a3 = fma2(wv[3][2 * i + 1], hy[i], a3);
        }
        float v0 = f2sum(a0), v1 = f2sum(a1), v2 = f2sum(a2), v3 = f2sum(a3);
#pragma unroll
        for (int d = 4; d <= 16; d <<= 1) {        // butterfly over 8 k-parts
            v0 += __shfl_xor_sync(0xffffffffu, v0, d);
            v1 += __shfl_xor_sync(0xffffffffu, v1, d);
            v2 += __shfl_xor_sync(0xffffffffu, v2, d);
            v3 += __shfl_xor_sync(0xffffffffu, v3, d);
        }

        if (writer) {
            v0 = tanh_fast(v0 + xc.x);
            v1 = tanh_fast(v1 + xc.y);
            v2 = tanh_fast(v2 + xc.z);
            v3 = tanh_fast(v3 + xc.w);
            if (s + 1 < T_SEQ) {
                unsigned long long p01 = packf2(v0, v1), p23 = packf2(v2, v3);
                stv2(lcw[sq], p01, p23);           // local chunk
                st_cluster_b64(rcw[sq],     p01);  // remote copy
                st_cluster_b64(rcw[sq] + 8, p23);
            }
            // off-critical-path tail
            *(float4*)(out + ((size_t)s * NB + b) * NH + j0) =
                make_float4(v0, v1, v2, v3);
            xc = x1;
            if (s + 2 < T_SEQ)
                x1 = *(const float4*)&g_xw[((size_t)(s + 2) * NB + b) * NH + j0];
        }
    }
    cluster_sync_();   // keep smem alive for in-flight peer stores
}

// =================================================================
extern "C" void kernel_launch(void* const* d_in, const int* in_sizes, int n_in,
                              void* d_out, int out_size) {
    const float* x    = (const float*)d_in[0];
    const float* w_ih = (const float*)d_in[1];
    const float* w_hh = (const float*)d_in[2];
    const float* b_ih = (const float*)d_in[3];
    const float* b_hh = (const float*)d_in[4];
    float* out = (float*)d_out;

    dim3 g1(1024, 2);
    xw_kernel<<<g1, 256>>>(x, w_ih, b_ih, b_hh);
    rnn_kernel<<<128, 256>>>(w_hh, out);
}